// round 1
// baseline (speedup 1.0000x reference)
#include <cuda_runtime.h>
#include <math.h>

// Problem constants (fixed by the reference)
#define NUM_K  1024
#define DIM    256
#define HWSZ   1024      // 32*32 spatial
#define NTOK   32768     // 32 * 1024
#define DECAYF 0.99f
#define OMD    0.01f     // 1 - decay
#define CCOST  0.25f
#define EPSF   1e-5f

// Output layout (flattened tuple, fp32):
// quantized_out [32,256,32,32] | loss | perplexity | new_codebook [1024,256]
// | new_cluster_size [1024] | new_ema_dw [1024,256]
#define OFF_Q    0
#define OFF_LOSS 8388608
#define OFF_PERP 8388609
#define OFF_CB   8388610
#define OFF_CS   8650754
#define OFF_EDW  8651778

// Scratch (device globals; no allocation allowed)
__device__ __align__(16) float g_dw[NUM_K * DIM];
__device__ float g_cnorm[NUM_K];
__device__ int   g_counts[NUM_K];
__device__ int   g_idx[NTOK];
__device__ float g_sumsq;
__device__ float g_csadj[NUM_K];

// ---------------------------------------------------------------------------
// K1: init scratch + codebook squared norms.  grid=1024, block=64
// ---------------------------------------------------------------------------
__global__ void k_init(const float* __restrict__ cb) {
    const int k = blockIdx.x;
    const int t = threadIdx.x;  // 0..63
    // zero dw row (64 * float4 = 256 floats)
    ((float4*)(g_dw + k * DIM))[t] = make_float4(0.f, 0.f, 0.f, 0.f);
    // cnorm
    const float4 c4 = ((const float4*)(cb + k * DIM))[t];
    float s = c4.x * c4.x + c4.y * c4.y + c4.z * c4.z + c4.w * c4.w;
    #pragma unroll
    for (int o = 16; o > 0; o >>= 1) s += __shfl_xor_sync(0xffffffffu, s, o);
    __shared__ float red[2];
    if ((t & 31) == 0) red[t >> 5] = s;
    __syncthreads();
    if (t == 0) {
        g_cnorm[k]  = red[0] + red[1];
        g_counts[k] = 0;
        if (k == 0) g_sumsq = 0.f;
    }
}

// ---------------------------------------------------------------------------
// K2: fused fp32 GEMM + argmin.  grid=256 CTAs (128 tokens each), block=256.
// score(n,k) = ||c_k||^2 - 2 * <z_n, c_k>  (||z||^2 constant per row).
// Register tile 8x8 per thread, 16x16 thread grid, double-buffered smem.
// ---------------------------------------------------------------------------
__global__ __launch_bounds__(256, 2)
void k_argmin(const float* __restrict__ z, const float* __restrict__ cb) {
    __shared__ __align__(16) float Zs[2][16][132];   // [buf][d][token]
    __shared__ float Cs[2][128][17];                 // [buf][k][d]

    const int tid = threadIdx.x;
    const int tx  = tid & 15;       // code column group
    const int ty  = tid >> 4;       // token row group
    const int tok0 = blockIdx.x * 128;
    const int b    = tok0 >> 10;          // 128 | 1024 -> single batch per CTA
    const int hw0  = tok0 & 1023;
    const float* zbase = z + (size_t)b * DIM * HWSZ + hw0;

    float acc[8][8];
    float minv[8];
    int   mini[8];
    #pragma unroll
    for (int i = 0; i < 8; i++) {
        minv[i] = 3.4e38f; mini[i] = 0;
        #pragma unroll
        for (int j = 0; j < 8; j++) acc[i][j] = 0.f;
    }

    // loader mapping
    const int zdl   = tid >> 4;   // 0..15  (d within chunk)
    const int zq    = tid & 15;   // 0..15  (token quad)
    const int ckk   = tid >> 1;   // 0..127 (code row)
    const int chalf = tid & 1;    // half of 16-d chunk

    auto load_chunk = [&](int it, int pbuf) {
        const int kt = it >> 4;
        const int dc = it & 15;
        // Z tile: 16 d x 128 tokens, coalesced along hw
        const float* zp = zbase + (size_t)(dc * 16 + zdl) * HWSZ;
        float4 v0 = *(const float4*)(zp + zq * 4);
        float4 v1 = *(const float4*)(zp + (zq + 16) * 4);
        *(float4*)&Zs[pbuf][zdl][zq * 4]        = v0;
        *(float4*)&Zs[pbuf][zdl][(zq + 16) * 4] = v1;
        // C tile: 128 codes x 16 d
        const float* cp = cb + (size_t)(kt * 128 + ckk) * DIM + dc * 16 + chalf * 8;
        float4 c0 = *(const float4*)cp;
        float4 c1 = *(const float4*)(cp + 4);
        float* cd = &Cs[pbuf][ckk][chalf * 8];
        cd[0] = c0.x; cd[1] = c0.y; cd[2] = c0.z; cd[3] = c0.w;
        cd[4] = c1.x; cd[5] = c1.y; cd[6] = c1.z; cd[7] = c1.w;
    };

    load_chunk(0, 0);
    __syncthreads();

    for (int it = 0; it < 128; ++it) {          // 8 k-tiles * 16 d-chunks
        const int p = it & 1;
        if (it + 1 < 128) load_chunk(it + 1, p ^ 1);

        #pragma unroll
        for (int d = 0; d < 16; ++d) {
            float a[8], bb[8];
            #pragma unroll
            for (int i = 0; i < 8; i++) a[i]  = Zs[p][d][ty + 16 * i];
            #pragma unroll
            for (int j = 0; j < 8; j++) bb[j] = Cs[p][tx + 16 * j][d];
            #pragma unroll
            for (int i = 0; i < 8; i++)
                #pragma unroll
                for (int j = 0; j < 8; j++)
                    acc[i][j] = fmaf(a[i], bb[j], acc[i][j]);
        }

        if ((it & 15) == 15) {                   // end of a k-tile: fold into argmin
            const int kt = it >> 4;
            #pragma unroll
            for (int j = 0; j < 8; j++) {
                const int k = kt * 128 + tx + 16 * j;   // ascending k per thread
                const float cn = g_cnorm[k];
                #pragma unroll
                for (int i = 0; i < 8; i++) {
                    float s = fmaf(-2.f, acc[i][j], cn);
                    if (s < minv[i]) { minv[i] = s; mini[i] = k; }
                    acc[i][j] = 0.f;
                }
            }
        }
        __syncthreads();
    }

    // cross-thread argmin reduce across tx (16-lane groups within warp)
    #pragma unroll
    for (int i = 0; i < 8; i++) {
        float v  = minv[i];
        int   ix = mini[i];
        #pragma unroll
        for (int off = 8; off >= 1; off >>= 1) {
            float ov = __shfl_xor_sync(0xffffffffu, v, off);
            int   oi = __shfl_xor_sync(0xffffffffu, ix, off);
            if (ov < v || (ov == v && oi < ix)) { v = ov; ix = oi; }
        }
        if (tx == 0) {
            const int tok = tok0 + ty + 16 * i;
            g_idx[tok] = ix;
            atomicAdd(&g_counts[ix], 1);
        }
    }
}

// ---------------------------------------------------------------------------
// K3: quantized output + dw scatter + loss partial. grid=1024 (32 tok), block=256
// ---------------------------------------------------------------------------
__global__ __launch_bounds__(256)
void k_scatter(const float* __restrict__ z, const float* __restrict__ cb,
               float* __restrict__ out) {
    const int tid  = threadIdx.x;
    const int lane = tid & 31;
    const int w    = tid >> 5;            // 8 warps
    const int tok0 = blockIdx.x * 32;
    const int b    = tok0 >> 10;
    const int hw   = (tok0 & 1023) + lane;
    const int tok  = tok0 + lane;
    const int k    = g_idx[tok];

    const float* zrow  = z  + (size_t)b * DIM * HWSZ + hw;
    float*       qrow  = out + OFF_Q + (size_t)b * DIM * HWSZ + hw;
    const float* crow  = cb + (size_t)k * DIM;
    float*       dwrow = g_dw + (size_t)k * DIM;

    float acc = 0.f;
    #pragma unroll 4
    for (int dd = 0; dd < 32; ++dd) {
        const int d = w + dd * 8;
        const float zv = zrow[(size_t)d * HWSZ];
        const float cv = crow[d];
        qrow[(size_t)d * HWSZ] = zv + (cv - zv);   // straight-through
        const float df = zv - cv;
        acc = fmaf(df, df, acc);
        atomicAdd(&dwrow[d], zv);
    }
    #pragma unroll
    for (int o = 16; o > 0; o >>= 1) acc += __shfl_xor_sync(0xffffffffu, acc, o);
    if (lane == 0) atomicAdd(&g_sumsq, acc);
}

// ---------------------------------------------------------------------------
// K4: cluster-size EMA, n-sum, perplexity, loss.  1 block, 1024 threads
// ---------------------------------------------------------------------------
__global__ void k_finalize1(const float* __restrict__ ema_cs, float* __restrict__ out) {
    __shared__ float red[32];
    __shared__ float nsh;
    const int k = threadIdx.x;

    const float cnt = (float)g_counts[k];
    const float ncs = ema_cs[k] * DECAYF + OMD * cnt;
    out[OFF_CS + k] = ncs;

    // n = sum(ncs)
    float s = ncs;
    #pragma unroll
    for (int o = 16; o > 0; o >>= 1) s += __shfl_xor_sync(0xffffffffu, s, o);
    if ((k & 31) == 0) red[k >> 5] = s;
    __syncthreads();
    if (k < 32) {
        float t = red[k];
        #pragma unroll
        for (int o = 16; o > 0; o >>= 1) t += __shfl_xor_sync(0xffffffffu, t, o);
        if (k == 0) nsh = t;
    }
    __syncthreads();
    const float n = nsh;
    g_csadj[k] = (ncs + EPSF) / (n + NUM_K * EPSF) * n;

    // perplexity
    const float p = cnt / (float)NTOK;
    float s2 = p * logf(p + 1e-10f);
    #pragma unroll
    for (int o = 16; o > 0; o >>= 1) s2 += __shfl_xor_sync(0xffffffffu, s2, o);
    if ((k & 31) == 0) red[k >> 5] = s2;
    __syncthreads();
    if (k == 0) {
        float t = 0.f;
        #pragma unroll
        for (int i = 0; i < 32; i++) t += red[i];
        out[OFF_PERP] = expf(-t);
        out[OFF_LOSS] = CCOST * g_sumsq / (float)(NTOK * DIM);
    }
}

// ---------------------------------------------------------------------------
// K5: ema_dw EMA + codebook division.  grid=1024, block=256
// ---------------------------------------------------------------------------
__global__ void k_finalize2(const float* __restrict__ ema_dw, float* __restrict__ out) {
    const int k = blockIdx.x;
    const int d = threadIdx.x;
    const size_t o = (size_t)k * DIM + d;
    const float nd = ema_dw[o] * DECAYF + OMD * g_dw[o];
    out[OFF_EDW + o] = nd;
    out[OFF_CB  + o] = nd / g_csadj[k];
}

// ---------------------------------------------------------------------------
extern "C" void kernel_launch(void* const* d_in, const int* in_sizes, int n_in,
                              void* d_out, int out_size) {
    const float* z      = (const float*)d_in[0];
    const float* cb     = (const float*)d_in[1];
    const float* ema_cs = (const float*)d_in[2];
    const float* ema_dw = (const float*)d_in[3];
    float* out = (float*)d_out;

    k_init<<<NUM_K, 64>>>(cb);
    k_argmin<<<NTOK / 128, 256>>>(z, cb);
    k_scatter<<<NTOK / 32, 256>>>(z, cb, out);
    k_finalize1<<<1, 1024>>>(ema_cs, out);
    k_finalize2<<<NUM_K, DIM>>>(ema_dw, out);
}